// round 1
// baseline (speedup 1.0000x reference)
#include <cuda_runtime.h>
#include <math.h>

#define BATCH 2
#define SEQ   8192
#define DM    1024
#define NH    16
#define DKH   64
#define MTOK  (BATCH*SEQ)
#define NCHUNK 16

// ---------------- scratch (static device globals; no allocations) ----------------
__device__ float g_q[(size_t)MTOK * DM];
__device__ float g_k[(size_t)MTOK * DM];
__device__ float g_v[(size_t)MTOK * DM];
__device__ float g_attn[(size_t)MTOK * DM];
__device__ float g_kvpart[NCHUNK * 32 * DKH * DKH];
__device__ float g_kspart[NCHUNK * 32 * DKH];
__device__ float g_kv[32 * DKH * DKH];
__device__ float g_ks[32 * DKH];

// ---------------- tf32 GEMM: C[M,N] = A[M,K] * W[N,K]^T + bias (+optional elu+1) ----
#define BM 128
#define BN 128
#define BK 32
#define SST 36                 // BK + 4 pad -> conflict-free fragment loads
#define ASTG (BM*SST)
#define BSTG (BN*SST)

__device__ __forceinline__ unsigned f2tf(float f) {
    unsigned u;
    asm("cvt.rna.tf32.f32 %0, %1;" : "=r"(u) : "f"(f));
    return u;
}

__device__ __forceinline__ void mma_tf32(float c[4], unsigned a0, unsigned a1,
                                         unsigned a2, unsigned a3,
                                         unsigned b0, unsigned b1) {
    asm volatile(
        "mma.sync.aligned.m16n8k8.row.col.f32.tf32.tf32.f32 "
        "{%0,%1,%2,%3},{%4,%5,%6,%7},{%8,%9},{%0,%1,%2,%3};\n"
        : "+f"(c[0]), "+f"(c[1]), "+f"(c[2]), "+f"(c[3])
        : "r"(a0), "r"(a1), "r"(a2), "r"(a3), "r"(b0), "r"(b1));
}

__global__ void __launch_bounds__(256, 1)
gemm_tf32(const float* __restrict__ A, const float* __restrict__ W,
          const float* __restrict__ bias, float* __restrict__ C, int fmap)
{
    extern __shared__ unsigned sh[];
    unsigned* As = sh;              // [2][BM*SST]
    unsigned* Bs = sh + 2 * ASTG;   // [2][BN*SST]

    const int tid  = threadIdx.x;
    const int lane = tid & 31, warp = tid >> 5;
    const int g  = lane >> 2, tg = lane & 3;
    const int wm = (warp >> 2) * 64;   // 0 / 64
    const int wn = (warp & 3) * 32;    // 0..96

    const int lr = tid >> 3;           // 0..31
    const int lv = tid & 7;            // 0..7

    const float* Ag = A + (size_t)(blockIdx.y * BM + lr) * DM + lv * 4;
    const float* Wg = W + (size_t)(blockIdx.x * BN + lr) * DM + lv * 4;

    float c[4][4][4];
    #pragma unroll
    for (int i = 0; i < 4; i++)
        #pragma unroll
        for (int j = 0; j < 4; j++) {
            c[i][j][0] = 0.f; c[i][j][1] = 0.f; c[i][j][2] = 0.f; c[i][j][3] = 0.f;
        }

    float4 ra[4], rb[4];
    #pragma unroll
    for (int i = 0; i < 4; i++) ra[i] = *(const float4*)(Ag + (size_t)i * 32 * DM);
    #pragma unroll
    for (int i = 0; i < 4; i++) rb[i] = *(const float4*)(Wg + (size_t)i * 32 * DM);

    const int sa = lr * SST + lv * 4;

    // store prologue tile into stage 0 (with rna tf32 conversion)
    #pragma unroll
    for (int i = 0; i < 4; i++) {
        uint4 u; u.x = f2tf(ra[i].x); u.y = f2tf(ra[i].y);
        u.z = f2tf(ra[i].z); u.w = f2tf(ra[i].w);
        *(uint4*)&As[sa + i * 32 * SST] = u;
    }
    #pragma unroll
    for (int i = 0; i < 4; i++) {
        uint4 u; u.x = f2tf(rb[i].x); u.y = f2tf(rb[i].y);
        u.z = f2tf(rb[i].z); u.w = f2tf(rb[i].w);
        *(uint4*)&Bs[sa + i * 32 * SST] = u;
    }
    __syncthreads();

    int aoff[4], boff[4];
    #pragma unroll
    for (int mt = 0; mt < 4; mt++) aoff[mt] = (wm + mt * 16 + g) * SST + tg;
    #pragma unroll
    for (int nt = 0; nt < 4; nt++) boff[nt] = (wn + nt * 8 + g) * SST + tg;

    const int NK = DM / BK;   // 32
    int stage = 0;
    for (int kt = 0; kt < NK; kt++) {
        if (kt + 1 < NK) {
            const float* Ap = Ag + (kt + 1) * BK;
            const float* Wp = Wg + (kt + 1) * BK;
            #pragma unroll
            for (int i = 0; i < 4; i++) ra[i] = *(const float4*)(Ap + (size_t)i * 32 * DM);
            #pragma unroll
            for (int i = 0; i < 4; i++) rb[i] = *(const float4*)(Wp + (size_t)i * 32 * DM);
        }
        const unsigned* as = As + stage * ASTG;
        const unsigned* bs = Bs + stage * BSTG;
        #pragma unroll
        for (int ks = 0; ks < 4; ks++) {
            const int kb = ks * 8;
            unsigned af[4][4], bf[4][2];
            #pragma unroll
            for (int mt = 0; mt < 4; mt++) {
                af[mt][0] = as[aoff[mt] + kb];
                af[mt][1] = as[aoff[mt] + 8 * SST + kb];
                af[mt][2] = as[aoff[mt] + kb + 4];
                af[mt][3] = as[aoff[mt] + 8 * SST + kb + 4];
            }
            #pragma unroll
            for (int nt = 0; nt < 4; nt++) {
                bf[nt][0] = bs[boff[nt] + kb];
                bf[nt][1] = bs[boff[nt] + kb + 4];
            }
            #pragma unroll
            for (int mt = 0; mt < 4; mt++)
                #pragma unroll
                for (int nt = 0; nt < 4; nt++)
                    mma_tf32(c[mt][nt], af[mt][0], af[mt][1], af[mt][2], af[mt][3],
                             bf[nt][0], bf[nt][1]);
        }
        if (kt + 1 < NK) {
            stage ^= 1;
            unsigned* das = As + stage * ASTG;
            unsigned* dbs = Bs + stage * BSTG;
            #pragma unroll
            for (int i = 0; i < 4; i++) {
                uint4 u; u.x = f2tf(ra[i].x); u.y = f2tf(ra[i].y);
                u.z = f2tf(ra[i].z); u.w = f2tf(ra[i].w);
                *(uint4*)&das[sa + i * 32 * SST] = u;
            }
            #pragma unroll
            for (int i = 0; i < 4; i++) {
                uint4 u; u.x = f2tf(rb[i].x); u.y = f2tf(rb[i].y);
                u.z = f2tf(rb[i].z); u.w = f2tf(rb[i].w);
                *(uint4*)&dbs[sa + i * 32 * SST] = u;
            }
        }
        __syncthreads();
    }

    // epilogue
    const int rbase = blockIdx.y * BM + wm + g;
    const int cbase = blockIdx.x * BN + wn + tg * 2;
    #pragma unroll
    for (int mt = 0; mt < 4; mt++) {
        #pragma unroll
        for (int nt = 0; nt < 4; nt++) {
            const int col = cbase + nt * 8;
            const float bb0 = bias[col], bb1 = bias[col + 1];
            const int r0 = rbase + mt * 16;
            float v00 = c[mt][nt][0] + bb0;
            float v01 = c[mt][nt][1] + bb1;
            float v10 = c[mt][nt][2] + bb0;
            float v11 = c[mt][nt][3] + bb1;
            if (fmap) {   // elu(x)+1 : x>0 ? x+1 : exp(x)
                v00 = v00 > 0.f ? v00 + 1.f : __expf(v00);
                v01 = v01 > 0.f ? v01 + 1.f : __expf(v01);
                v10 = v10 > 0.f ? v10 + 1.f : __expf(v10);
                v11 = v11 > 0.f ? v11 + 1.f : __expf(v11);
            }
            C[(size_t)r0 * DM + col]           = v00;
            C[(size_t)r0 * DM + col + 1]       = v01;
            C[(size_t)(r0 + 8) * DM + col]     = v10;
            C[(size_t)(r0 + 8) * DM + col + 1] = v11;
        }
    }
}

// ---------------- kv partial: per (chunk, b, h) accumulate 64x64 + k_sum ---------
__global__ void __launch_bounds__(256)
kv_partial()
{
    const int chunk = blockIdx.x;
    const int bh = blockIdx.y;
    const int b = bh >> 4, h = bh & 15;
    const int t = threadIdx.x;
    const int i = t >> 2, tg = t & 3;
    __shared__ float ks[8 * 64], vs[8 * 64];

    const float* kb = g_k + (size_t)(b * SEQ) * DM + h * DKH;
    const float* vb = g_v + (size_t)(b * SEQ) * DM + h * DKH;

    float4 acc[4];
    #pragma unroll
    for (int q = 0; q < 4; q++) acc[q] = make_float4(0.f, 0.f, 0.f, 0.f);
    float ksacc = 0.f;

    const int n_begin = chunk * (SEQ / NCHUNK);
    const int n_end   = n_begin + SEQ / NCHUNK;
    for (int n0 = n_begin; n0 < n_end; n0 += 8) {
        __syncthreads();
        {
            int e = t;
            ks[e] = kb[(size_t)(n0 + (e >> 6)) * DM + (e & 63)];
            vs[e] = vb[(size_t)(n0 + (e >> 6)) * DM + (e & 63)];
            e = t + 256;
            ks[e] = kb[(size_t)(n0 + (e >> 6)) * DM + (e & 63)];
            vs[e] = vb[(size_t)(n0 + (e >> 6)) * DM + (e & 63)];
        }
        __syncthreads();
        #pragma unroll
        for (int r = 0; r < 8; r++) {
            const float kv = ks[r * 64 + i];
            if (tg == 0) ksacc += kv;
            const float4* vr = (const float4*)(vs + r * 64 + tg * 16);
            #pragma unroll
            for (int q = 0; q < 4; q++) {
                float4 vv = vr[q];
                acc[q].x += kv * vv.x; acc[q].y += kv * vv.y;
                acc[q].z += kv * vv.z; acc[q].w += kv * vv.w;
            }
        }
    }
    float* kvp = g_kvpart + (size_t)(chunk * 32 + bh) * DKH * DKH + i * DKH + tg * 16;
    #pragma unroll
    for (int q = 0; q < 4; q++) *(float4*)(kvp + q * 4) = acc[q];
    if (tg == 0) g_kspart[(chunk * 32 + bh) * DKH + i] = ksacc;
}

// ---------------- reduce partials ------------------------------------------------
__global__ void __launch_bounds__(256)
kv_reduce()
{
    const int bh = blockIdx.x;
    const int t = threadIdx.x;
    for (int e = t; e < DKH * DKH; e += 256) {
        float s = 0.f;
        #pragma unroll
        for (int cc = 0; cc < NCHUNK; cc++)
            s += g_kvpart[(size_t)(cc * 32 + bh) * (DKH * DKH) + e];
        g_kv[bh * DKH * DKH + e] = s;
    }
    if (t < DKH) {
        float s = 0.f;
        #pragma unroll
        for (int cc = 0; cc < NCHUNK; cc++)
            s += g_kspart[(cc * 32 + bh) * DKH + t];
        g_ks[bh * DKH + t] = s;
    }
}

// ---------------- qkv + normalizer ----------------------------------------------
__global__ void __launch_bounds__(256)
qkv_norm()
{
    const int tile = blockIdx.x;
    const int bh = blockIdx.y;
    const int b = bh >> 4, h = bh & 15;
    const int t = threadIdx.x;
    __shared__ float kvs[DKH * DKH];
    __shared__ float qs[DKH * 65];
    __shared__ float ksums[DKH];
    __shared__ float norms[DKH];

    for (int e = t; e < DKH * DKH; e += 256) kvs[e] = g_kv[bh * DKH * DKH + e];
    if (t < DKH) ksums[t] = g_ks[bh * DKH + t];

    const int n0 = tile * 64;
    const float* qb = g_q + (size_t)(b * SEQ + n0) * DM + h * DKH;
    for (int e = t; e < 4096; e += 256) {
        const int r = e >> 6, d = e & 63;
        qs[r * 65 + d] = qb[(size_t)r * DM + d];
    }
    __syncthreads();

    if (t < 64) {
        float s = 0.f;
        #pragma unroll
        for (int d = 0; d < 64; d++) s += qs[t * 65 + d] * ksums[d];
        norms[t] = 1.0f / (s + 1e-6f);
    }
    __syncthreads();

    const int r = t >> 2, tg = t & 3;
    float4 acc[4];
    #pragma unroll
    for (int q = 0; q < 4; q++) acc[q] = make_float4(0.f, 0.f, 0.f, 0.f);

    #pragma unroll 8
    for (int d = 0; d < 64; d++) {
        const float qv = qs[r * 65 + d];
        const float4* kr = (const float4*)(kvs + d * 64 + tg * 16);
        #pragma unroll
        for (int q = 0; q < 4; q++) {
            float4 kk = kr[q];
            acc[q].x += qv * kk.x; acc[q].y += qv * kk.y;
            acc[q].z += qv * kk.z; acc[q].w += qv * kk.w;
        }
    }
    const float inv = norms[r];
    float* ob = g_attn + (size_t)(b * SEQ + n0 + r) * DM + h * DKH + tg * 16;
    #pragma unroll
    for (int q = 0; q < 4; q++) {
        float4 o;
        o.x = acc[q].x * inv; o.y = acc[q].y * inv;
        o.z = acc[q].z * inv; o.w = acc[q].w * inv;
        *(float4*)(ob + q * 4) = o;
    }
}

// ---------------- launcher -------------------------------------------------------
extern "C" void kernel_launch(void* const* d_in, const int* in_sizes, int n_in,
                              void* d_out, int out_size)
{
    const float* query = (const float*)d_in[0];
    const float* key   = (const float*)d_in[1];
    const float* value = (const float*)d_in[2];
    const float* wq = (const float*)d_in[3];
    const float* bq = (const float*)d_in[4];
    const float* wk = (const float*)d_in[5];
    const float* bk = (const float*)d_in[6];
    const float* wv = (const float*)d_in[7];
    const float* bv = (const float*)d_in[8];
    const float* wo = (const float*)d_in[9];
    const float* bo = (const float*)d_in[10];
    float* out = (float*)d_out;

    float *qb, *kb, *vb, *attn;
    cudaGetSymbolAddress((void**)&qb,   g_q);
    cudaGetSymbolAddress((void**)&kb,   g_k);
    cudaGetSymbolAddress((void**)&vb,   g_v);
    cudaGetSymbolAddress((void**)&attn, g_attn);

    const int shmem = 2 * (ASTG + BSTG) * (int)sizeof(unsigned);  // 73728 B
    cudaFuncSetAttribute(gemm_tf32, cudaFuncAttributeMaxDynamicSharedMemorySize, shmem);

    dim3 gg(DM / BN, MTOK / BM);   // (8, 128)
    gemm_tf32<<<gg, 256, shmem>>>(query, wq, bq, qb, 1);
    gemm_tf32<<<gg, 256, shmem>>>(key,   wk, bk, kb, 1);
    gemm_tf32<<<gg, 256, shmem>>>(value, wv, bv, vb, 0);

    kv_partial<<<dim3(NCHUNK, 32), 256>>>();
    kv_reduce<<<32, 256>>>();
    qkv_norm<<<dim3(SEQ / 64, 32), 256>>>();

    gemm_tf32<<<gg, 256, shmem>>>(attn, wo, bo, out, 0);
}

// round 2
// speedup vs baseline: 1.3497x; 1.3497x over previous
#include <cuda_runtime.h>
#include <math.h>

#define BATCH 2
#define SEQ   8192
#define DM    1024
#define NH    16
#define DKH   64
#define MTOK  (BATCH*SEQ)
#define NCHUNK 16

// ---------------- scratch (static device globals; no allocations) ----------------
__device__ float g_q[(size_t)MTOK * DM];
__device__ float g_k[(size_t)MTOK * DM];
__device__ float g_v[(size_t)MTOK * DM];
__device__ float g_attn[(size_t)MTOK * DM];
__device__ float g_kvpart[NCHUNK * 32 * DKH * DKH];
__device__ float g_kspart[NCHUNK * 32 * DKH];
__device__ float g_kv[32 * DKH * DKH];
__device__ float g_ks[32 * DKH];

// ---------------- tf32 GEMM: C[M,N] = A[M,K] * W[N,K]^T + bias (+optional elu+1) ----
#define BM 128
#define BN 128
#define BK 32
#define SST 36                 // BK + 4 pad -> conflict-free fragment loads
#define ASTG (BM*SST)
#define BSTG (BN*SST)

__device__ __forceinline__ unsigned f2tf(float f) {
    unsigned u;
    asm("cvt.rna.tf32.f32 %0, %1;" : "=r"(u) : "f"(f));
    return u;
}

__device__ __forceinline__ void mma_tf32(float c[4], unsigned a0, unsigned a1,
                                         unsigned a2, unsigned a3,
                                         unsigned b0, unsigned b1) {
    asm volatile(
        "mma.sync.aligned.m16n8k8.row.col.f32.tf32.tf32.f32 "
        "{%0,%1,%2,%3},{%4,%5,%6,%7},{%8,%9},{%0,%1,%2,%3};\n"
        : "+f"(c[0]), "+f"(c[1]), "+f"(c[2]), "+f"(c[3])
        : "r"(a0), "r"(a1), "r"(a2), "r"(a3), "r"(b0), "r"(b1));
}

__global__ void __launch_bounds__(256, 1)
gemm_tf32(const float* __restrict__ A, const float* __restrict__ W,
          const float* __restrict__ bias, float* __restrict__ C, int fmap)
{
    extern __shared__ unsigned sh[];
    unsigned* As = sh;              // [2][BM*SST]
    unsigned* Bs = sh + 2 * ASTG;   // [2][BN*SST]

    const int tid  = threadIdx.x;
    const int lane = tid & 31, warp = tid >> 5;
    const int g  = lane >> 2, tg = lane & 3;
    const int wm = (warp >> 2) * 64;   // 0 / 64
    const int wn = (warp & 3) * 32;    // 0..96

    const int lr = tid >> 3;           // 0..31
    const int lv = tid & 7;            // 0..7

    const float* Ag = A + (size_t)(blockIdx.y * BM + lr) * DM + lv * 4;
    const float* Wg = W + (size_t)(blockIdx.x * BN + lr) * DM + lv * 4;

    float c[4][4][4];
    #pragma unroll
    for (int i = 0; i < 4; i++)
        #pragma unroll
        for (int j = 0; j < 4; j++) {
            c[i][j][0] = 0.f; c[i][j][1] = 0.f; c[i][j][2] = 0.f; c[i][j][3] = 0.f;
        }

    float4 ra[4], rb[4];
    #pragma unroll
    for (int i = 0; i < 4; i++) ra[i] = *(const float4*)(Ag + (size_t)i * 32 * DM);
    #pragma unroll
    for (int i = 0; i < 4; i++) rb[i] = *(const float4*)(Wg + (size_t)i * 32 * DM);

    const int sa = lr * SST + lv * 4;

    #pragma unroll
    for (int i = 0; i < 4; i++) {
        uint4 u; u.x = f2tf(ra[i].x); u.y = f2tf(ra[i].y);
        u.z = f2tf(ra[i].z); u.w = f2tf(ra[i].w);
        *(uint4*)&As[sa + i * 32 * SST] = u;
    }
    #pragma unroll
    for (int i = 0; i < 4; i++) {
        uint4 u; u.x = f2tf(rb[i].x); u.y = f2tf(rb[i].y);
        u.z = f2tf(rb[i].z); u.w = f2tf(rb[i].w);
        *(uint4*)&Bs[sa + i * 32 * SST] = u;
    }
    __syncthreads();

    int aoff[4], boff[4];
    #pragma unroll
    for (int mt = 0; mt < 4; mt++) aoff[mt] = (wm + mt * 16 + g) * SST + tg;
    #pragma unroll
    for (int nt = 0; nt < 4; nt++) boff[nt] = (wn + nt * 8 + g) * SST + tg;

    const int NK = DM / BK;   // 32
    int stage = 0;
    for (int kt = 0; kt < NK; kt++) {
        if (kt + 1 < NK) {
            const float* Ap = Ag + (kt + 1) * BK;
            const float* Wp = Wg + (kt + 1) * BK;
            #pragma unroll
            for (int i = 0; i < 4; i++) ra[i] = *(const float4*)(Ap + (size_t)i * 32 * DM);
            #pragma unroll
            for (int i = 0; i < 4; i++) rb[i] = *(const float4*)(Wp + (size_t)i * 32 * DM);
        }
        const unsigned* as = As + stage * ASTG;
        const unsigned* bs = Bs + stage * BSTG;
        #pragma unroll
        for (int ks = 0; ks < 4; ks++) {
            const int kb = ks * 8;
            unsigned af[4][4], bf[4][2];
            #pragma unroll
            for (int mt = 0; mt < 4; mt++) {
                af[mt][0] = as[aoff[mt] + kb];
                af[mt][1] = as[aoff[mt] + 8 * SST + kb];
                af[mt][2] = as[aoff[mt] + kb + 4];
                af[mt][3] = as[aoff[mt] + 8 * SST + kb + 4];
            }
            #pragma unroll
            for (int nt = 0; nt < 4; nt++) {
                bf[nt][0] = bs[boff[nt] + kb];
                bf[nt][1] = bs[boff[nt] + kb + 4];
            }
            #pragma unroll
            for (int mt = 0; mt < 4; mt++)
                #pragma unroll
                for (int nt = 0; nt < 4; nt++)
                    mma_tf32(c[mt][nt], af[mt][0], af[mt][1], af[mt][2], af[mt][3],
                             bf[nt][0], bf[nt][1]);
        }
        if (kt + 1 < NK) {
            stage ^= 1;
            unsigned* das = As + stage * ASTG;
            unsigned* dbs = Bs + stage * BSTG;
            #pragma unroll
            for (int i = 0; i < 4; i++) {
                uint4 u; u.x = f2tf(ra[i].x); u.y = f2tf(ra[i].y);
                u.z = f2tf(ra[i].z); u.w = f2tf(ra[i].w);
                *(uint4*)&das[sa + i * 32 * SST] = u;
            }
            #pragma unroll
            for (int i = 0; i < 4; i++) {
                uint4 u; u.x = f2tf(rb[i].x); u.y = f2tf(rb[i].y);
                u.z = f2tf(rb[i].z); u.w = f2tf(rb[i].w);
                *(uint4*)&dbs[sa + i * 32 * SST] = u;
            }
        }
        __syncthreads();
    }

    const int rbase = blockIdx.y * BM + wm + g;
    const int cbase = blockIdx.x * BN + wn + tg * 2;
    #pragma unroll
    for (int mt = 0; mt < 4; mt++) {
        #pragma unroll
        for (int nt = 0; nt < 4; nt++) {
            const int col = cbase + nt * 8;
            const float bb0 = bias[col], bb1 = bias[col + 1];
            const int r0 = rbase + mt * 16;
            float v00 = c[mt][nt][0] + bb0;
            float v01 = c[mt][nt][1] + bb1;
            float v10 = c[mt][nt][2] + bb0;
            float v11 = c[mt][nt][3] + bb1;
            if (fmap) {
                v00 = v00 > 0.f ? v00 + 1.f : __expf(v00);
                v01 = v01 > 0.f ? v01 + 1.f : __expf(v01);
                v10 = v10 > 0.f ? v10 + 1.f : __expf(v10);
                v11 = v11 > 0.f ? v11 + 1.f : __expf(v11);
            }
            C[(size_t)r0 * DM + col]           = v00;
            C[(size_t)r0 * DM + col + 1]       = v01;
            C[(size_t)(r0 + 8) * DM + col]     = v10;
            C[(size_t)(r0 + 8) * DM + col + 1] = v11;
        }
    }
}

// ---------------- kv partial v2: 4x4 register tiles, 32-row staged chunks --------
// out[d][m] += sum_n k[n][d] * v[n][m];  block = (chunk, bh), 256 threads
#define CROWS 32
__global__ void __launch_bounds__(256)
kv_partial()
{
    const int chunk = blockIdx.x;
    const int bh = blockIdx.y;
    const int b = bh >> 4, h = bh & 15;
    const int t = threadIdx.x;
    const int d0 = (t >> 4) * 4;     // 4 d-rows (16 lanes share -> broadcast)
    const int m0 = (t & 15) * 4;     // 4 m-cols

    __shared__ float ks[CROWS * 64];
    __shared__ float vs[CROWS * 64];

    const float* kb = g_k + (size_t)(b * SEQ) * DM + h * DKH;
    const float* vb = g_v + (size_t)(b * SEQ) * DM + h * DKH;

    float4 acc[4];
    #pragma unroll
    for (int i = 0; i < 4; i++) acc[i] = make_float4(0.f, 0.f, 0.f, 0.f);
    float4 ksacc = make_float4(0.f, 0.f, 0.f, 0.f);

    // staging map: idx in [0,512) float4s; row = idx/16, col4 = idx%16
    const int i0 = t, i1 = t + 256;
    const int r0s = i0 >> 4, c0s = (i0 & 15) * 4;
    const int r1s = i1 >> 4, c1s = (i1 & 15) * 4;

    const int n_begin = chunk * (SEQ / NCHUNK);

    // prefetch chunk 0
    float4 pk0 = *(const float4*)(kb + (size_t)(n_begin + r0s) * DM + c0s);
    float4 pk1 = *(const float4*)(kb + (size_t)(n_begin + r1s) * DM + c1s);
    float4 pv0 = *(const float4*)(vb + (size_t)(n_begin + r0s) * DM + c0s);
    float4 pv1 = *(const float4*)(vb + (size_t)(n_begin + r1s) * DM + c1s);

    const int NCH = (SEQ / NCHUNK) / CROWS;  // 16
    for (int c = 0; c < NCH; c++) {
        __syncthreads();
        *(float4*)&ks[r0s * 64 + c0s] = pk0;
        *(float4*)&ks[r1s * 64 + c1s] = pk1;
        *(float4*)&vs[r0s * 64 + c0s] = pv0;
        *(float4*)&vs[r1s * 64 + c1s] = pv1;
        __syncthreads();
        if (c + 1 < NCH) {
            const int nn = n_begin + (c + 1) * CROWS;
            pk0 = *(const float4*)(kb + (size_t)(nn + r0s) * DM + c0s);
            pk1 = *(const float4*)(kb + (size_t)(nn + r1s) * DM + c1s);
            pv0 = *(const float4*)(vb + (size_t)(nn + r0s) * DM + c0s);
            pv1 = *(const float4*)(vb + (size_t)(nn + r1s) * DM + c1s);
        }
        #pragma unroll
        for (int r = 0; r < CROWS; r++) {
            const float4 kf = *(const float4*)&ks[r * 64 + d0];
            const float4 vf = *(const float4*)&vs[r * 64 + m0];
            acc[0].x += kf.x * vf.x; acc[0].y += kf.x * vf.y;
            acc[0].z += kf.x * vf.z; acc[0].w += kf.x * vf.w;
            acc[1].x += kf.y * vf.x; acc[1].y += kf.y * vf.y;
            acc[1].z += kf.y * vf.z; acc[1].w += kf.y * vf.w;
            acc[2].x += kf.z * vf.x; acc[2].y += kf.z * vf.y;
            acc[2].z += kf.z * vf.z; acc[2].w += kf.z * vf.w;
            acc[3].x += kf.w * vf.x; acc[3].y += kf.w * vf.y;
            acc[3].z += kf.w * vf.z; acc[3].w += kf.w * vf.w;
            if ((t & 15) == 0) {
                ksacc.x += kf.x; ksacc.y += kf.y;
                ksacc.z += kf.z; ksacc.w += kf.w;
            }
        }
    }

    float* kvp = g_kvpart + (size_t)(chunk * 32 + bh) * (DKH * DKH);
    #pragma unroll
    for (int i = 0; i < 4; i++)
        *(float4*)(kvp + (d0 + i) * DKH + m0) = acc[i];
    if ((t & 15) == 0) {
        float* ksp = g_kspart + (chunk * 32 + bh) * DKH + d0;
        ksp[0] = ksacc.x; ksp[1] = ksacc.y; ksp[2] = ksacc.z; ksp[3] = ksacc.w;
    }
}

// ---------------- reduce partials ------------------------------------------------
__global__ void __launch_bounds__(256)
kv_reduce()
{
    const int bh = blockIdx.x;
    const int t = threadIdx.x;
    for (int e = t; e < DKH * DKH; e += 256) {
        float s = 0.f;
        #pragma unroll
        for (int cc = 0; cc < NCHUNK; cc++)
            s += g_kvpart[(size_t)(cc * 32 + bh) * (DKH * DKH) + e];
        g_kv[bh * DKH * DKH + e] = s;
    }
    if (t < DKH) {
        float s = 0.f;
        #pragma unroll
        for (int cc = 0; cc < NCHUNK; cc++)
            s += g_kspart[(cc * 32 + bh) * DKH + t];
        g_ks[bh * DKH + t] = s;
    }
}

// ---------------- qkv + normalizer v2: 4x4 register tiles -----------------------
// out[r][m] = (sum_d q[r][d]*kv[d][m]) / (q[r]·ksum + eps); 64-row tile per block
#define QPAD 68
__global__ void __launch_bounds__(256)
qkv_norm()
{
    const int tile = blockIdx.x;
    const int bh = blockIdx.y;
    const int b = bh >> 4, h = bh & 15;
    const int t = threadIdx.x;
    const int r0 = (t >> 4) * 4;     // 4 rows (16 lanes share -> broadcast)
    const int m0 = (t & 15) * 4;     // 4 cols

    __shared__ float kvs[DKH * DKH];
    __shared__ float qs[DKH * QPAD];
    __shared__ float ksums[DKH];
    __shared__ float norms[DKH];

    // load kv (4096 floats) as float4
    #pragma unroll
    for (int j = 0; j < 4; j++) {
        const int idx = t + j * 256;
        *(float4*)&kvs[idx * 4] = *(const float4*)&g_kv[(size_t)bh * (DKH * DKH) + idx * 4];
    }
    if (t < DKH) ksums[t] = g_ks[bh * DKH + t];

    const int n0 = tile * 64;
    const float* qb = g_q + (size_t)(b * SEQ + n0) * DM + h * DKH;
    #pragma unroll
    for (int j = 0; j < 4; j++) {
        const int idx = t + j * 256;           // 0..1023
        const int rr = idx >> 4, cc = (idx & 15) * 4;
        *(float4*)&qs[rr * QPAD + cc] = *(const float4*)(qb + (size_t)rr * DM + cc);
    }
    __syncthreads();

    if (t < 64) {
        float s = 0.f;
        #pragma unroll
        for (int d = 0; d < 64; d += 4) {
            const float4 qf = *(const float4*)&qs[t * QPAD + d];
            s += qf.x * ksums[d] + qf.y * ksums[d + 1]
               + qf.z * ksums[d + 2] + qf.w * ksums[d + 3];
        }
        norms[t] = 1.0f / (s + 1e-6f);
    }
    __syncthreads();

    float4 acc[4];
    #pragma unroll
    for (int i = 0; i < 4; i++) acc[i] = make_float4(0.f, 0.f, 0.f, 0.f);

    #pragma unroll
    for (int dc = 0; dc < 16; dc++) {
        const int dd = dc * 4;
        float4 qf[4];
        #pragma unroll
        for (int i = 0; i < 4; i++)
            qf[i] = *(const float4*)&qs[(r0 + i) * QPAD + dd];   // broadcast
        #pragma unroll
        for (int u = 0; u < 4; u++) {
            const float4 kvf = *(const float4*)&kvs[(dd + u) * 64 + m0];
            const float q0 = (u == 0) ? qf[0].x : (u == 1) ? qf[0].y : (u == 2) ? qf[0].z : qf[0].w;
            const float q1 = (u == 0) ? qf[1].x : (u == 1) ? qf[1].y : (u == 2) ? qf[1].z : qf[1].w;
            const float q2 = (u == 0) ? qf[2].x : (u == 1) ? qf[2].y : (u == 2) ? qf[2].z : qf[2].w;
            const float q3 = (u == 0) ? qf[3].x : (u == 1) ? qf[3].y : (u == 2) ? qf[3].z : qf[3].w;
            acc[0].x += q0 * kvf.x; acc[0].y += q0 * kvf.y;
            acc[0].z += q0 * kvf.z; acc[0].w += q0 * kvf.w;
            acc[1].x += q1 * kvf.x; acc[1].y += q1 * kvf.y;
            acc[1].z += q1 * kvf.z; acc[1].w += q1 * kvf.w;
            acc[2].x += q2 * kvf.x; acc[2].y += q2 * kvf.y;
            acc[2].z += q2 * kvf.z; acc[2].w += q2 * kvf.w;
            acc[3].x += q3 * kvf.x; acc[3].y += q3 * kvf.y;
            acc[3].z += q3 * kvf.z; acc[3].w += q3 * kvf.w;
        }
    }

    #pragma unroll
    for (int i = 0; i < 4; i++) {
        const float inv = norms[r0 + i];
        float4 o;
        o.x = acc[i].x * inv; o.y = acc[i].y * inv;
        o.z = acc[i].z * inv; o.w = acc[i].w * inv;
        *(float4*)(g_attn + (size_t)(b * SEQ + n0 + r0 + i) * DM + h * DKH + m0) = o;
    }
}

// ---------------- launcher -------------------------------------------------------
extern "C" void kernel_launch(void* const* d_in, const int* in_sizes, int n_in,
                              void* d_out, int out_size)
{
    const float* query = (const float*)d_in[0];
    const float* key   = (const float*)d_in[1];
    const float* value = (const float*)d_in[2];
    const float* wq = (const float*)d_in[3];
    const float* bq = (const float*)d_in[4];
    const float* wk = (const float*)d_in[5];
    const float* bk = (const float*)d_in[6];
    const float* wv = (const float*)d_in[7];
    const float* bv = (const float*)d_in[8];
    const float* wo = (const float*)d_in[9];
    const float* bo = (const float*)d_in[10];
    float* out = (float*)d_out;

    float *qb, *kb, *vb, *attn;
    cudaGetSymbolAddress((void**)&qb,   g_q);
    cudaGetSymbolAddress((void**)&kb,   g_k);
    cudaGetSymbolAddress((void**)&vb,   g_v);
    cudaGetSymbolAddress((void**)&attn, g_attn);

    const int shmem = 2 * (ASTG + BSTG) * (int)sizeof(unsigned);  // 73728 B
    cudaFuncSetAttribute(gemm_tf32, cudaFuncAttributeMaxDynamicSharedMemorySize, shmem);

    dim3 gg(DM / BN, MTOK / BM);   // (8, 128)
    gemm_tf32<<<gg, 256, shmem>>>(query, wq, bq, qb, 1);
    gemm_tf32<<<gg, 256, shmem>>>(key,   wk, bk, kb, 1);
    gemm_tf32<<<gg, 256, shmem>>>(value, wv, bv, vb, 0);

    kv_partial<<<dim3(NCHUNK, 32), 256>>>();
    kv_reduce<<<32, 256>>>();
    qkv_norm<<<dim3(SEQ / 64, 32), 256>>>();

    gemm_tf32<<<gg, 256, shmem>>>(attn, wo, bo, out, 0);
}

// round 4
// speedup vs baseline: 1.4515x; 1.0754x over previous
#include <cuda_runtime.h>
#include <cuda_fp16.h>
#include <math.h>
#include <stdint.h>

#define BATCH 2
#define SEQ   8192
#define DM    1024
#define NH    16
#define DKH   64
#define MTOK  (BATCH*SEQ)
#define NCHUNK 16

// ---------------- scratch (static device globals; no allocations) ----------------
__device__ float g_q[(size_t)MTOK * DM];
__device__ float g_k[(size_t)MTOK * DM];
__device__ float g_v[(size_t)MTOK * DM];
__device__ float g_attn[(size_t)MTOK * DM];
__device__ float g_kvpart[NCHUNK * 32 * DKH * DKH];
__device__ float g_kspart[NCHUNK * 32 * DKH];
__device__ float g_kv[32 * DKH * DKH];
__device__ float g_ks[32 * DKH];

// ---------------- helpers ---------------------------------------------------------
__device__ __forceinline__ uint32_t smem_u32(const void* p) {
    uint32_t a;
    asm("{ .reg .u64 t; cvta.to.shared.u64 t, %1; cvt.u32.u64 %0, t; }"
        : "=r"(a) : "l"(p));
    return a;
}

__device__ __forceinline__ uint32_t pack_h2(float x, float y) {
    __half2 h = __floats2half2_rn(x, y);
    return reinterpret_cast<uint32_t&>(h);
}

__device__ __forceinline__ void ldsm4(uint32_t& r0, uint32_t& r1, uint32_t& r2,
                                      uint32_t& r3, uint32_t a) {
    asm volatile("ldmatrix.sync.aligned.m8n8.x4.shared.b16 {%0,%1,%2,%3}, [%4];"
                 : "=r"(r0), "=r"(r1), "=r"(r2), "=r"(r3) : "r"(a));
}

__device__ __forceinline__ void mma_f16(float c[4], const uint32_t a[4],
                                        uint32_t b0, uint32_t b1) {
    asm volatile(
        "mma.sync.aligned.m16n8k16.row.col.f32.f16.f16.f32 "
        "{%0,%1,%2,%3},{%4,%5,%6,%7},{%8,%9},{%0,%1,%2,%3};"
        : "+f"(c[0]), "+f"(c[1]), "+f"(c[2]), "+f"(c[3])
        : "r"(a[0]), "r"(a[1]), "r"(a[2]), "r"(a[3]), "r"(b0), "r"(b1));
}

// ---------------- fp16 GEMM: C[M,N] = A[M,K] * W[N,K]^T + bias (+elu+1) -----------
#define BM 128
#define BN 128
#define BK 32
#define SSTH 40                 // halves per row (32 + 8 pad -> conflict-free LDSM)
#define ATILE (BM*SSTH)         // 5120 halves per A (or B) tile
#define STG (2*ATILE)           // halves per stage (A + B)

__global__ void __launch_bounds__(256, 1)
gemm_f16(const float* __restrict__ A, const float* __restrict__ W,
         const float* __restrict__ bias, float* __restrict__ C, int fmap)
{
    __shared__ __align__(16) __half sh[2 * STG];   // 40960 B

    const int t    = threadIdx.x;
    const int lane = t & 31, warp = t >> 5;
    const int g  = lane >> 2, tg = lane & 3;
    const int wm = (warp >> 2) * 64;   // 0 / 64
    const int wn = (warp & 3) * 32;    // 0..96

    const int lr = t >> 3;             // 0..31 (row group)
    const int lv = t & 7;              // 0..7  (col group of 4 floats)

    const float* Ag = A + (size_t)(blockIdx.y * BM + lr) * DM + lv * 4;
    const float* Wg = W + (size_t)(blockIdx.x * BN + lr) * DM + lv * 4;

    float c[4][4][4];
    #pragma unroll
    for (int i = 0; i < 4; i++)
        #pragma unroll
        for (int j = 0; j < 4; j++) {
            c[i][j][0] = 0.f; c[i][j][1] = 0.f; c[i][j][2] = 0.f; c[i][j][3] = 0.f;
        }

    // ldmatrix per-lane offsets (in halves)
    const int sub = lane >> 3, r8 = lane & 7;
    const int aoff = (r8 + (sub & 1) * 8) * SSTH + (sub >> 1) * 8;
    const int boff = (r8 + (sub >> 1) * 8) * SSTH + (sub & 1) * 8;
    const uint32_t sbase = smem_u32(sh);
    const uint32_t aAddr0 = sbase + 2u * (uint32_t)(wm * SSTH + aoff);
    const uint32_t bAddr0 = sbase + 2u * (uint32_t)(ATILE + wn * SSTH + boff);

    // prologue: load k-tile 0, convert, store stage 0
    float4 ra[4], rb[4];
    #pragma unroll
    for (int i = 0; i < 4; i++) ra[i] = *(const float4*)(Ag + (size_t)i * 32 * DM);
    #pragma unroll
    for (int i = 0; i < 4; i++) rb[i] = *(const float4*)(Wg + (size_t)i * 32 * DM);

    {
        __half* dst = sh;
        const int so = lr * SSTH + lv * 4;
        #pragma unroll
        for (int i = 0; i < 4; i++) {
            uint2 u; u.x = pack_h2(ra[i].x, ra[i].y); u.y = pack_h2(ra[i].z, ra[i].w);
            *(uint2*)&dst[so + i * 32 * SSTH] = u;
        }
        #pragma unroll
        for (int i = 0; i < 4; i++) {
            uint2 u; u.x = pack_h2(rb[i].x, rb[i].y); u.y = pack_h2(rb[i].z, rb[i].w);
            *(uint2*)&dst[ATILE + so + i * 32 * SSTH] = u;
        }
    }
    __syncthreads();

    const int NK = DM / BK;   // 32
    int stage = 0;
    for (int kt = 0; kt < NK; kt++) {
        if (kt + 1 < NK) {
            const float* Ap = Ag + (kt + 1) * BK;
            const float* Wp = Wg + (kt + 1) * BK;
            #pragma unroll
            for (int i = 0; i < 4; i++) ra[i] = *(const float4*)(Ap + (size_t)i * 32 * DM);
            #pragma unroll
            for (int i = 0; i < 4; i++) rb[i] = *(const float4*)(Wp + (size_t)i * 32 * DM);
        }

        const uint32_t stoff = (uint32_t)(stage * STG * 2);
        #pragma unroll
        for (int ks = 0; ks < 2; ks++) {
            const uint32_t kb2 = (uint32_t)(ks * 16 * 2);
            uint32_t af[4][4], bf[4][2];
            #pragma unroll
            for (int mt = 0; mt < 4; mt++)
                ldsm4(af[mt][0], af[mt][1], af[mt][2], af[mt][3],
                      aAddr0 + stoff + (uint32_t)(mt * 16 * SSTH * 2) + kb2);
            ldsm4(bf[0][0], bf[0][1], bf[1][0], bf[1][1], bAddr0 + stoff + kb2);
            ldsm4(bf[2][0], bf[2][1], bf[3][0], bf[3][1],
                  bAddr0 + stoff + (uint32_t)(16 * SSTH * 2) + kb2);
            #pragma unroll
            for (int mt = 0; mt < 4; mt++)
                #pragma unroll
                for (int nt = 0; nt < 4; nt++)
                    mma_f16(c[mt][nt], af[mt], bf[nt][0], bf[nt][1]);
        }

        if (kt + 1 < NK) {
            stage ^= 1;
            __half* dst = sh + stage * STG;
            const int so = lr * SSTH + lv * 4;
            #pragma unroll
            for (int i = 0; i < 4; i++) {
                uint2 u; u.x = pack_h2(ra[i].x, ra[i].y); u.y = pack_h2(ra[i].z, ra[i].w);
                *(uint2*)&dst[so + i * 32 * SSTH] = u;
            }
            #pragma unroll
            for (int i = 0; i < 4; i++) {
                uint2 u; u.x = pack_h2(rb[i].x, rb[i].y); u.y = pack_h2(rb[i].z, rb[i].w);
                *(uint2*)&dst[ATILE + so + i * 32 * SSTH] = u;
            }
        }
        __syncthreads();
    }

    // epilogue (c layout identical to tf32 m16n8 layout)
    const int rbase = blockIdx.y * BM + wm + g;
    const int cbase = blockIdx.x * BN + wn + tg * 2;
    #pragma unroll
    for (int mt = 0; mt < 4; mt++) {
        #pragma unroll
        for (int nt = 0; nt < 4; nt++) {
            const int col = cbase + nt * 8;
            const float bb0 = bias[col], bb1 = bias[col + 1];
            const int r0 = rbase + mt * 16;
            float v00 = c[mt][nt][0] + bb0;
            float v01 = c[mt][nt][1] + bb1;
            float v10 = c[mt][nt][2] + bb0;
            float v11 = c[mt][nt][3] + bb1;
            if (fmap) {   // elu(x)+1
                v00 = v00 > 0.f ? v00 + 1.f : __expf(v00);
                v01 = v01 > 0.f ? v01 + 1.f : __expf(v01);
                v10 = v10 > 0.f ? v10 + 1.f : __expf(v10);
                v11 = v11 > 0.f ? v11 + 1.f : __expf(v11);
            }
            C[(size_t)r0 * DM + col]           = v00;
            C[(size_t)r0 * DM + col + 1]       = v01;
            C[(size_t)(r0 + 8) * DM + col]     = v10;
            C[(size_t)(r0 + 8) * DM + col + 1] = v11;
        }
    }
}

// ---------------- kv partial: 4x4 register tiles, 32-row staged chunks -----------
#define CROWS 32
__global__ void __launch_bounds__(256)
kv_partial()
{
    const int chunk = blockIdx.x;
    const int bh = blockIdx.y;
    const int b = bh >> 4, h = bh & 15;
    const int t = threadIdx.x;
    const int d0 = (t >> 4) * 4;
    const int m0 = (t & 15) * 4;

    __shared__ float ks[CROWS * 64];
    __shared__ float vs[CROWS * 64];

    const float* kb = g_k + (size_t)(b * SEQ) * DM + h * DKH;
    const float* vb = g_v + (size_t)(b * SEQ) * DM + h * DKH;

    float4 acc[4];
    #pragma unroll
    for (int i = 0; i < 4; i++) acc[i] = make_float4(0.f, 0.f, 0.f, 0.f);
    float4 ksacc = make_float4(0.f, 0.f, 0.f, 0.f);

    const int i0 = t, i1 = t + 256;
    const int r0s = i0 >> 4, c0s = (i0 & 15) * 4;
    const int r1s = i1 >> 4, c1s = (i1 & 15) * 4;

    const int n_begin = chunk * (SEQ / NCHUNK);

    float4 pk0 = *(const float4*)(kb + (size_t)(n_begin + r0s) * DM + c0s);
    float4 pk1 = *(const float4*)(kb + (size_t)(n_begin + r1s) * DM + c1s);
    float4 pv0 = *(const float4*)(vb + (size_t)(n_begin + r0s) * DM + c0s);
    float4 pv1 = *(const float4*)(vb + (size_t)(n_begin + r1s) * DM + c1s);

    const int NCH = (SEQ / NCHUNK) / CROWS;
    for (int c = 0; c < NCH; c++) {
        __syncthreads();
        *(float4*)&ks[r0s * 64 + c0s] = pk0;
        *(float4*)&ks[r1s * 64 + c1s] = pk1;
        *(float4*)&vs[r0s * 64 + c0s] = pv0;
        *(float4*)&vs[r1s * 64 + c1s] = pv1;
        __syncthreads();
        if (c + 1 < NCH) {
            const int nn = n_begin + (c + 1) * CROWS;
            pk0 = *(const float4*)(kb + (size_t)(nn + r0s) * DM + c0s);
            pk1 = *(const float4*)(kb + (size_t)(nn + r1s) * DM + c1s);
            pv0 = *(const float4*)(vb + (size_t)(nn + r0s) * DM + c0s);
            pv1 = *(const float4*)(vb + (size_t)(nn + r1s) * DM + c1s);
        }
        #pragma unroll
        for (int r = 0; r < CROWS; r++) {
            const float4 kf = *(const float4*)&ks[r * 64 + d0];
            const float4 vf = *(const float4*)&vs[r * 64 + m0];
            acc[0].x += kf.x * vf.x; acc[0].y += kf.x * vf.y;
            acc[0].z += kf.x * vf.z; acc[0].w += kf.x * vf.w;
            acc[1].x += kf.y * vf.x; acc[1].y += kf.y * vf.y;
            acc[1].z += kf.y * vf.z; acc[1].w += kf.y * vf.w;
            acc[2].x += kf.z * vf.x; acc[2].y += kf.z * vf.y;
            acc[2].z += kf.z * vf.z; acc[2].w += kf.z * vf.w;
            acc[3].x += kf.w * vf.x; acc[3].y += kf.w * vf.y;
            acc[3].z += kf.w * vf.z; acc[3].w += kf.w * vf.w;
            if ((t & 15) == 0) {
                ksacc.x += kf.x; ksacc.y += kf.y;
                ksacc.z += kf.z; ksacc.w += kf.w;
            }
        }
    }

    float* kvp = g_kvpart + (size_t)(chunk * 32 + bh) * (DKH * DKH);
    #pragma unroll
    for (int i = 0; i < 4; i++)
        *(float4*)(kvp + (d0 + i) * DKH + m0) = acc[i];
    if ((t & 15) == 0) {
        float* ksp = g_kspart + (chunk * 32 + bh) * DKH + d0;
        ksp[0] = ksacc.x; ksp[1] = ksacc.y; ksp[2] = ksacc.z; ksp[3] = ksacc.w;
    }
}

// ---------------- reduce partials ------------------------------------------------
__global__ void __launch_bounds__(256)
kv_reduce()
{
    const int bh = blockIdx.x;
    const int t = threadIdx.x;
    for (int e = t; e < DKH * DKH; e += 256) {
        float s = 0.f;
        #pragma unroll
        for (int cc = 0; cc < NCHUNK; cc++)
            s += g_kvpart[(size_t)(cc * 32 + bh) * (DKH * DKH) + e];
        g_kv[bh * DKH * DKH + e] = s;
    }
    if (t < DKH) {
        float s = 0.f;
        #pragma unroll
        for (int cc = 0; cc < NCHUNK; cc++)
            s += g_kspart[(cc * 32 + bh) * DKH + t];
        g_ks[bh * DKH + t] = s;
    }
}

// ---------------- qkv + normalizer: 4x4 register tiles ---------------------------
#define QPAD 68
__global__ void __launch_bounds__(256)
qkv_norm()
{
    const int tile = blockIdx.x;
    const int bh = blockIdx.y;
    const int b = bh >> 4, h = bh & 15;
    const int t = threadIdx.x;
    const int r0 = (t >> 4) * 4;
    const int m0 = (t & 15) * 4;

    __shared__ float kvs[DKH * DKH];
    __shared__ float qs[DKH * QPAD];
    __shared__ float ksums[DKH];
    __shared__ float norms[DKH];

    #pragma unroll
    for (int j = 0; j < 4; j++) {
        const int idx = t + j * 256;
        *(float4*)&kvs[idx * 4] = *(const float4*)&g_kv[(size_t)bh * (DKH * DKH) + idx * 4];
    }
    if (t < DKH) ksums[t] = g_ks[bh * DKH + t];

    const int n0 = tile * 64;
    const float* qb = g_q + (size_t)(b * SEQ + n0) * DM + h * DKH;
    #pragma unroll
    for (int j = 0; j < 4; j++) {
        const int idx = t + j * 256;
        const int rr = idx >> 4, cc = (idx & 15) * 4;
        *(float4*)&qs[rr * QPAD + cc] = *(const float4*)(qb + (size_t)rr * DM + cc);
    }
    __syncthreads();

    if (t < 64) {
        float s = 0.f;
        #pragma unroll
        for (int d = 0; d < 64; d += 4) {
            const float4 qf = *(const float4*)&qs[t * QPAD + d];
            s += qf.x * ksums[d] + qf.y * ksums[d + 1]
               + qf.z * ksums[d + 2] + qf.w * ksums[d + 3];
        }
        norms[t] = 1.0f / (s + 1e-6f);
    }
    __syncthreads();

    float4 acc[4];
    #pragma unroll
    for (int i = 0; i < 4; i++) acc[i] = make_float4(0.f, 0.f, 0.f, 0.f);

    #pragma unroll
    for (int dc = 0; dc < 16; dc++) {
        const int dd = dc * 4;
        float4 qf[4];
        #pragma unroll
        for (int i = 0; i < 4; i++)
            qf[i] = *(const float4*)&qs[(r0 + i) * QPAD + dd];
        #pragma unroll
        for (int u = 0; u < 4; u++) {
            const float4 kvf = *(const float4*)&kvs[(dd + u) * 64 + m0];
            const float q0 = (u == 0) ? qf[0].x : (u == 1) ? qf[0].y : (u == 2) ? qf[0].z : qf[0].w;
            const float q1 = (u == 0) ? qf[1].x : (u == 1) ? qf[1].y : (u == 2) ? qf[1].z : qf[1].w;
            const float q2 = (u == 0) ? qf[2].x : (u == 1) ? qf[2].y : (u == 2) ? qf[2].z : qf[2].w;
            const float q3 = (u == 0) ? qf[3].x : (u == 1) ? qf[3].y : (u == 2) ? qf[3].z : qf[3].w;
            acc[0].x += q0 * kvf.x; acc[0].y += q0 * kvf.y;
            acc[0].z += q0 * kvf.z; acc[0].w += q0 * kvf.w;
            acc[1].x += q1 * kvf.x; acc[1].y += q1 * kvf.y;
            acc[1].z += q1 * kvf.z; acc[1].w += q1 * kvf.w;
            acc[2].x += q2 * kvf.x; acc[2].y += q2 * kvf.y;
            acc[2].z += q2 * kvf.z; acc[2].w += q2 * kvf.w;
            acc[3].x += q3 * kvf.x; acc[3].y += q3 * kvf.y;
            acc[3].z += q3 * kvf.z; acc[3].w += q3 * kvf.w;
        }
    }

    #pragma unroll
    for (int i = 0; i < 4; i++) {
        const float inv = norms[r0 + i];
        float4 o;
        o.x = acc[i].x * inv; o.y = acc[i].y * inv;
        o.z = acc[i].z * inv; o.w = acc[i].w * inv;
        *(float4*)(g_attn + (size_t)(b * SEQ + n0 + r0 + i) * DM + h * DKH + m0) = o;
    }
}

// ---------------- launcher -------------------------------------------------------
extern "C" void kernel_launch(void* const* d_in, const int* in_sizes, int n_in,
                              void* d_out, int out_size)
{
    const float* query = (const float*)d_in[0];
    const float* key   = (const float*)d_in[1];
    const float* value = (const float*)d_in[2];
    const float* wq = (const float*)d_in[3];
    const float* bq = (const float*)d_in[4];
    const float* wk = (const float*)d_in[5];
    const float* bk = (const float*)d_in[6];
    const float* wv = (const float*)d_in[7];
    const float* bv = (const float*)d_in[8];
    const float* wo = (const float*)d_in[9];
    const float* bo = (const float*)d_in[10];
    float* out = (float*)d_out;

    float *qb, *kb, *vb, *attn;
    cudaGetSymbolAddress((void**)&qb,   g_q);
    cudaGetSymbolAddress((void**)&kb,   g_k);
    cudaGetSymbolAddress((void**)&vb,   g_v);
    cudaGetSymbolAddress((void**)&attn, g_attn);

    dim3 gg(DM / BN, MTOK / BM);   // (8, 128)
    gemm_f16<<<gg, 256>>>(query, wq, bq, qb, 1);
    gemm_f16<<<gg, 256>>>(key,   wk, bk, kb, 1);
    gemm_f16<<<gg, 256>>>(value, wv, bv, vb, 0);

    kv_partial<<<dim3(NCHUNK, 32), 256>>>();
    kv_reduce<<<32, 256>>>();
    qkv_norm<<<dim3(SEQ / 64, 32), 256>>>();

    gemm_f16<<<gg, 256>>>(attn, wo, bo, out, 0);
}